// round 9
// baseline (speedup 1.0000x reference)
#include <cuda_runtime.h>
#include <cstdint>

// Fixed shapes per reference: B=256, L=512, N=50000
constexpr int B_SZ   = 256;
constexpr int L_SEQ  = 512;
constexpr int N_LOC  = 50000;
constexpr int HSIZE  = 1024;                 // hash slots (pow2), load factor 0.5
constexpr int NT     = 512;
constexpr int ROW_BYTES = N_LOC * 4;         // 200,000
constexpr int BUF_BYTES = 25600;             // smem zero buffer (16B multiple)
constexpr int N_COPIES  = 4;                 // one per issuing warp
constexpr int TMA_BYTES = BUF_BYTES * N_COPIES;   // 102,400 (head of row)
constexpr int STG_BYTES = ROW_BYTES - TMA_BYTES;  // 97,600 (tail of row)
constexpr int STG_V8    = STG_BYTES / 32;         // 3,050 v8 stores per row

__device__ __forceinline__ uint32_t smem_u32(const void* p) {
    uint32_t a;
    asm("{ .reg .u64 t; cvta.to.shared.u64 t, %1; cvt.u32.u64 %0, t; }" : "=r"(a) : "l"(p));
    return a;
}

__global__ __launch_bounds__(NT, 2)
void fused_kernel(const int* __restrict__ loc_seq,
                  const int* __restrict__ mask,
                  const float* __restrict__ rw_p,
                  const float* __restrict__ fw_p,
                  float* __restrict__ out)
{
    const int b   = blockIdx.x;              // one CTA per batch row
    const int tid = threadIdx.x;

    __shared__ float4   buf[BUF_BYTES / 16]; // zero source for bulk copies
    __shared__ int      h_key[HSIZE];
    __shared__ int      h_cnt[HSIZE];
    __shared__ unsigned h_rec[HSIZE];        // float bits; all values >= 0
    __shared__ int      s_maxcnt;

    // ---- init zero buffer + hash (parallel across 512 threads) ----
    const float4 z = make_float4(0.f, 0.f, 0.f, 0.f);
    #pragma unroll
    for (int i = tid; i < BUF_BYTES / 16; i += NT) buf[i] = z;
    #pragma unroll
    for (int i = tid; i < HSIZE; i += NT) {
        h_key[i] = -1;
        h_cnt[i] = 0;
        h_rec[i] = 0u;
    }
    if (tid == 0) s_maxcnt = 0;
    __syncthreads();
    // order generic smem writes before async-proxy reads of buf
    asm volatile("fence.proxy.async.shared::cta;" ::: "memory");

    char* const rowc = (char*)out + (size_t)b * ROW_BYTES;

    // ---- 4 warps each launch one 25.6 KB bulk-zero of the row head ----
    const bool issuer = ((tid & 31) == 0) && (tid < 128);
    if (issuer) {
        const int c = tid >> 5;              // 0..3
        asm volatile(
            "cp.async.bulk.global.shared::cta.bulk_group [%0], [%1], %2;"
            :: "l"(rowc + c * BUF_BYTES), "r"(smem_u32(buf)), "r"(BUF_BYTES)
            : "memory");
        asm volatile("cp.async.bulk.commit_group;" ::: "memory");
    }

    // ---- concurrently zero the row tail with 256-bit stores (LSU path) ----
    {
        float* p = (float*)(rowc + TMA_BYTES);
        #pragma unroll 2
        for (int i = tid; i < STG_V8; i += NT) {
            asm volatile(
                "st.global.v8.f32 [%0], {%1,%2,%3,%4,%5,%6,%7,%8};"
                :: "l"(p + i * 8),
                   "f"(0.f), "f"(0.f), "f"(0.f), "f"(0.f),
                   "f"(0.f), "f"(0.f), "f"(0.f), "f"(0.f)
                : "memory");
        }
    }

    // ---- build the row hash ONCE (1 timestep per thread), hidden under TMA ----
    const float l2rw = log2f(*rw_p);
    {
        const int t   = tid;
        const int key = loc_seq[(size_t)b * L_SEQ + t];
        const int m   = mask   [(size_t)b * L_SEQ + t];
        const float rec = m ? exp2f((float)(L_SEQ - 1 - t) * l2rw) : 0.0f;

        unsigned h = ((unsigned)key * 2654435761u) & (HSIZE - 1);
        for (;;) {
            int cur = h_key[h];
            if (cur == key) break;
            if (cur == -1) {
                int prev = atomicCAS(&h_key[h], -1, key);
                if (prev == -1 || prev == key) break;
            }
            h = (h + 1) & (HSIZE - 1);
        }
        atomicAdd(&h_cnt[h], m);
        atomicMax(&h_rec[h], __float_as_uint(rec));
    }
    __syncthreads();

    // ---- block reduce: max frequency count (2 slots per thread) ----
    int mf = max(h_cnt[tid], h_cnt[tid + NT]);
    #pragma unroll
    for (int o = 16; o > 0; o >>= 1) mf = max(mf, __shfl_xor_sync(0xFFFFFFFFu, mf, o));
    if ((tid & 31) == 0) atomicMax(&s_maxcnt, mf);

    // ---- wait for own bulk-zero copies (purely local dependency) ----
    if (issuer)
        asm volatile("cp.async.bulk.wait_group 0;" ::: "memory");
    __syncthreads();

    const float inv = (*fw_p) / fmaxf((float)s_maxcnt, 1.0f);

    // ---- scatter final values over the zeroed row (2 slots per thread) ----
    float* row = out + (size_t)b * N_LOC;
    #pragma unroll
    for (int i = tid; i < HSIZE; i += NT) {
        const int key = h_key[i];
        if (key >= 0) {
            row[key] = __uint_as_float(h_rec[i]) + (float)h_cnt[i] * inv;
        }
    }
}

extern "C" void kernel_launch(void* const* d_in, const int* in_sizes, int n_in,
                              void* d_out, int out_size)
{
    const int*   loc_seq = (const int*)  d_in[0];   // (B, L) int32
    const int*   mask    = (const int*)  d_in[1];   // (B, L) int32
    const float* rw      = (const float*)d_in[2];   // scalar
    const float* fw      = (const float*)d_in[3];   // scalar
    float*       out     = (float*)d_out;           // (B, N) float32

    fused_kernel<<<B_SZ, NT>>>(loc_seq, mask, rw, fw, out);
}